// round 16
// baseline (speedup 1.0000x reference)
#include <cuda_runtime.h>
#include <cuda_bf16.h>
#include <cuda_fp16.h>
#include <cstdint>

#define N_NODES 100000
#define N_EDGES 800000
#define SCAN_CHUNK 400

// ------------------------- device scratch (no allocs) ------------------------
__device__ __align__(16) __half g_xh[(size_t)N_NODES * 64];    // x as fp16
__device__ __align__(16) float  g_z1[(size_t)N_NODES * 64];
__device__ __align__(16) __half g_h [(size_t)N_NODES * 128];   // layer1 out (fp16)
__device__ __align__(16) float  g_z2[(size_t)N_NODES * 128];
__device__ int g_cnt[N_NODES];          // zero at load; re-zeroed by scan_emit each call
__device__ int g_off[N_NODES + 1];
__device__ int g_cur[N_NODES];
__device__ int g_esrc[N_EDGES];
__device__ int g_bsum[512];

// ------------------------------ fp16 helpers ---------------------------------
__device__ __forceinline__ unsigned pkh(float x, float y) {
    __half2 h = __floats2half2_rn(x, y);
    return *reinterpret_cast<unsigned*>(&h);
}
__device__ __forceinline__ void split2h(float x, float y, unsigned& hi, unsigned& lo) {
    float xh = __half2float(__float2half_rn(x));
    float yh = __half2float(__float2half_rn(y));
    hi = pkh(x, y);
    lo = pkh(x - xh, y - yh);
}
// unpack uint2 (4 halves) and accumulate into float4
__device__ __forceinline__ void acc_h4(float4& a, uint2 p) {
    float2 v0 = __half22float2(*reinterpret_cast<__half2*>(&p.x));
    float2 v1 = __half22float2(*reinterpret_cast<__half2*>(&p.y));
    a.x += v0.x; a.y += v0.y; a.z += v1.x; a.w += v1.y;
}
// m16n8k16 fp16 MMA, fp32 accumulate
__device__ __forceinline__ void mma_f16(float* c, const unsigned* a, const unsigned* b) {
    asm volatile(
        "mma.sync.aligned.m16n8k16.row.col.f32.f16.f16.f32 "
        "{%0,%1,%2,%3}, {%4,%5,%6,%7}, {%8,%9}, {%0,%1,%2,%3};"
        : "+f"(c[0]), "+f"(c[1]), "+f"(c[2]), "+f"(c[3])
        : "r"(a[0]), "r"(a[1]), "r"(a[2]), "r"(a[3]), "r"(b[0]), "r"(b[1]));
}

// ------------------------------ CSR build ------------------------------------
__global__ void hist_kernel(const int* __restrict__ dst, int* __restrict__ cnt, int n_edges) {
    int e = blockIdx.x * blockDim.x + threadIdx.x;
    if (e < n_edges) atomicAdd(&cnt[dst[e]], 1);
}
__global__ void scan_part_kernel(const int* __restrict__ cnt, int* __restrict__ bsum, int n) {
    __shared__ int red[256];
    int b = blockIdx.x, t = threadIdx.x;
    int s = 0;
    for (int i = t; i < SCAN_CHUNK; i += 256) {
        int idx = b * SCAN_CHUNK + i;
        if (idx < n) s += cnt[idx];
    }
    red[t] = s;
    __syncthreads();
    for (int d = 128; d > 0; d >>= 1) {
        if (t < d) red[t] += red[t + d];
        __syncthreads();
    }
    if (t == 0) bsum[b] = red[0];
}
__global__ void scan_emit_kernel(int* __restrict__ cnt, const int* __restrict__ bsum,
                                 int* __restrict__ off, int* __restrict__ cur,
                                 int n, int n_edges) {
    __shared__ int s[512];
    __shared__ int red[256];
    int b = blockIdx.x, t = threadIdx.x;
    int acc = 0;
    for (int i = t; i < b; i += 256) acc += bsum[i];
    red[t] = acc;
    __syncthreads();
    for (int d = 128; d > 0; d >>= 1) {
        if (t < d) red[t] += red[t + d];
        __syncthreads();
    }
    int base = red[0];
    #pragma unroll
    for (int h = 0; h < 2; h++) {
        int i = t + h * 256;
        int idx = b * SCAN_CHUNK + i;
        s[i] = (i < SCAN_CHUNK && idx < n) ? cnt[idx] : 0;
    }
    __syncthreads();
    for (int d = 1; d < 512; d <<= 1) {
        int v0 = (t >= d) ? s[t - d] : 0;
        int v1 = s[t + 256 - d];
        __syncthreads();
        s[t] += v0;
        s[t + 256] += v1;
        __syncthreads();
    }
    #pragma unroll
    for (int h = 0; h < 2; h++) {
        int i = t + h * 256;
        int idx = b * SCAN_CHUNK + i;
        if (i < SCAN_CHUNK && idx < n) {
            int excl = base + (i ? s[i - 1] : 0);
            off[idx] = excl;
            cur[idx] = excl;
            cnt[idx] = 0;
        }
    }
    if (b == 0 && t == 0) off[n] = n_edges;
}
__global__ void fill_kernel(const int* __restrict__ src, const int* __restrict__ dst,
                            int* __restrict__ cur, int* __restrict__ esrc, int n_edges) {
    int e = blockIdx.x * blockDim.x + threadIdx.x;
    if (e >= n_edges) return;
    int d = dst[e];
    int p = atomicAdd(&cur[d], 1);
    esrc[p] = src[e];
}

// ---------------------- x -> fp16 conversion (one pass) ----------------------
__global__ void cvt_half_kernel(const float4* __restrict__ in, uint2* __restrict__ out, int n4) {
    int i = blockIdx.x * blockDim.x + threadIdx.x;
    if (i >= n4) return;
    float4 v = in[i];
    out[i] = make_uint2(pkh(v.x, v.y), pkh(v.z, v.w));
}

// --------------------- gather aggregation:  z = (1+eps)x + sum ---------------
// layer-1: x fp16, half-warp per node, lane l covers k = 4l..4l+3 (one LDG.64)
__global__ void gather64h_kernel(const __half* __restrict__ xh,
                                 const int* __restrict__ off,
                                 const int* __restrict__ esrc,
                                 const float* __restrict__ eps,
                                 float* __restrict__ z, int n_nodes) {
    int gwarp = (blockIdx.x * blockDim.x + threadIdx.x) >> 5;
    int lane = threadIdx.x & 31;
    int node = gwarp * 2 + (lane >> 4);
    int l = lane & 15;
    if (node >= n_nodes) return;
    const uint2* base = reinterpret_cast<const uint2*>(xh);
    uint2 sp = __ldg(base + (size_t)node * 16 + l);
    float4 a0 = make_float4(0.f, 0.f, 0.f, 0.f);
    float4 a1 = make_float4(0.f, 0.f, 0.f, 0.f);
    int e0 = off[node], e1 = off[node + 1];
    int e = e0;
    for (; e + 1 < e1; e += 2) {
        int s0 = __ldg(&esrc[e]);
        int s1 = __ldg(&esrc[e + 1]);
        uint2 p0 = __ldg(base + (size_t)s0 * 16 + l);
        uint2 p1 = __ldg(base + (size_t)s1 * 16 + l);
        acc_h4(a0, p0);
        acc_h4(a1, p1);
    }
    if (e < e1) {
        int s0 = __ldg(&esrc[e]);
        acc_h4(a0, __ldg(base + (size_t)s0 * 16 + l));
    }
    a0.x += a1.x; a0.y += a1.y; a0.z += a1.z; a0.w += a1.w;
    float2 s0 = __half22float2(*reinterpret_cast<__half2*>(&sp.x));
    float2 s1 = __half22float2(*reinterpret_cast<__half2*>(&sp.y));
    float sc = 1.0f + *eps;
    float4 r = make_float4(fmaf(sc, s0.x, a0.x), fmaf(sc, s0.y, a0.y),
                           fmaf(sc, s1.x, a0.z), fmaf(sc, s1.y, a0.w));
    reinterpret_cast<float4*>(z + (size_t)node * 64)[l] = r;
}
// layer-2: h fp16, full warp per node, lane l covers k = 4l..4l+3 (one LDG.64)
__global__ void gather128h_kernel(const __half* __restrict__ h,
                                  const int* __restrict__ off,
                                  const int* __restrict__ esrc,
                                  const float* __restrict__ eps,
                                  float* __restrict__ z, int n_nodes) {
    int node = (blockIdx.x * blockDim.x + threadIdx.x) >> 5;
    int l = threadIdx.x & 31;
    if (node >= n_nodes) return;
    const uint2* base = reinterpret_cast<const uint2*>(h);
    uint2 sp = __ldg(base + (size_t)node * 32 + l);
    float4 a0 = make_float4(0.f, 0.f, 0.f, 0.f);
    float4 a1 = make_float4(0.f, 0.f, 0.f, 0.f);
    int e0 = off[node], e1 = off[node + 1];
    int e = e0;
    for (; e + 1 < e1; e += 2) {
        int s0 = __ldg(&esrc[e]);
        int s1 = __ldg(&esrc[e + 1]);
        uint2 p0 = __ldg(base + (size_t)s0 * 32 + l);
        uint2 p1 = __ldg(base + (size_t)s1 * 32 + l);
        acc_h4(a0, p0);
        acc_h4(a1, p1);
    }
    if (e < e1) {
        int s0 = __ldg(&esrc[e]);
        acc_h4(a0, __ldg(base + (size_t)s0 * 32 + l));
    }
    a0.x += a1.x; a0.y += a1.y; a0.z += a1.z; a0.w += a1.w;
    float2 s0 = __half22float2(*reinterpret_cast<__half2*>(&sp.x));
    float2 s1 = __half22float2(*reinterpret_cast<__half2*>(&sp.y));
    float sc = 1.0f + *eps;
    float4 r = make_float4(fmaf(sc, s0.x, a0.x), fmaf(sc, s0.y, a0.y),
                           fmaf(sc, s1.x, a0.z), fmaf(sc, s1.y, a0.w));
    reinterpret_cast<float4*>(z + (size_t)node * 128)[l] = r;
}

// ----------- MMA MLP: fp16 A-split (exact) x fp16 weights, 2 passes ----------
// Persistent grid, TILE=128 nodes, 512 threads (16 warps). Warp (mt, nh):
// m-tile mt (16 rows), n-half nh. Weights transposed n-major fp16 (single).
// OUT_HALF: write output as __half (layer-1 h buffer), else float.
template <int D_IN, int D_OUT, bool RELU_OUT, bool OUT_HALF>
__global__ void __launch_bounds__(512, 1)
mlp_mma_kernel(const float* __restrict__ z,
               const float* __restrict__ Wa, const float* __restrict__ ba,
               const float* __restrict__ Wb, const float* __restrict__ bb,
               void* __restrict__ out, int n_nodes, int ntiles) {
    constexpr int DH = 128, TILE = 128, THREADS = 512;
    constexpr int PA1 = D_IN + 8;
    constexpr int PA2 = DH + 8;
    constexpr int KT1 = D_IN / 16, KT2 = DH / 16;
    constexpr int NT1 = 8;            // stage1: 64 cols per n-half / 8
    constexpr int NT2 = D_OUT / 16;   // stage2 n-tiles per half
    constexpr int SZ_WaT = DH * PA1 * 2;
    constexpr int SZ_WbT = D_OUT * PA2 * 2;
    constexpr int SZ_Z = TILE * PA1 * 2;
    constexpr int SZ_H = TILE * PA2 * 2;
    constexpr int O_WaH = 0;
    constexpr int O_WbH = SZ_WaT;
    constexpr int O_ZH = O_WbH + SZ_WbT, O_ZL = O_ZH + SZ_Z;
    constexpr int O_HH = O_ZL + SZ_Z, O_HL = O_HH + SZ_H;
    constexpr int O_BA = O_HL + SZ_H, O_BB = O_BA + DH * 4;

    extern __shared__ char sm[];
    unsigned short* WaH = (unsigned short*)(sm + O_WaH);
    unsigned short* WbH = (unsigned short*)(sm + O_WbH);
    const unsigned* WaH32 = (const unsigned*)WaH;
    const unsigned* WbH32 = (const unsigned*)WbH;
    unsigned* zH32 = (unsigned*)(sm + O_ZH);
    unsigned* zL32 = (unsigned*)(sm + O_ZL);
    unsigned* hH32 = (unsigned*)(sm + O_HH);
    unsigned* hL32 = (unsigned*)(sm + O_HL);
    float* ba_s = (float*)(sm + O_BA);
    float* bb_s = (float*)(sm + O_BB);

    const int tid = threadIdx.x;
    const int wid = tid >> 5, lane = tid & 31;
    const int g = lane >> 2, q = lane & 3;
    const int mt = wid >> 1, nh = wid & 1;
    const int r0 = mt * 16 + g;

    // ---- stage weights once per CTA (fp16, n-major) ----
    for (int i = tid; i < D_IN * DH; i += THREADS) {
        int k = i / DH, n = i % DH;
        WaH[n * PA1 + k] = __half_as_ushort(__float2half_rn(Wa[i]));
    }
    for (int i = tid; i < DH * D_OUT; i += THREADS) {
        int k = i / D_OUT, n = i % D_OUT;
        WbH[n * PA2 + k] = __half_as_ushort(__float2half_rn(Wb[i]));
    }
    if (tid < DH) ba_s[tid] = ba[tid];
    if (tid < D_OUT) bb_s[tid] = bb[tid];
    __syncthreads();

    for (int t = blockIdx.x; t < ntiles; t += gridDim.x) {
        const int tile0 = t * TILE;

        // ---- stage z tile: split into hi/lo fp16 [row][k] ----
        for (int i = tid; i < TILE * (D_IN / 4); i += THREADS) {
            int r = i / (D_IN / 4);
            int kc = i % (D_IN / 4);
            int node = tile0 + r;
            float4 v = (node < n_nodes)
                     ? reinterpret_cast<const float4*>(z + (size_t)node * D_IN)[kc]
                     : make_float4(0.f, 0.f, 0.f, 0.f);
            unsigned h0, l0, h1, l1;
            split2h(v.x, v.y, h0, l0);
            split2h(v.z, v.w, h1, l1);
            int idx = r * (PA1 / 2) + kc * 2;
            *reinterpret_cast<uint2*>(zH32 + idx) = make_uint2(h0, h1);
            *reinterpret_cast<uint2*>(zL32 + idx) = make_uint2(l0, l1);
        }
        __syncthreads();

        // ---- stage 1: hidden = relu(z @ Wa + ba) ----
        float c1[NT1][4];
        #pragma unroll
        for (int nt = 0; nt < NT1; nt++)
            #pragma unroll
            for (int j = 0; j < 4; j++) c1[nt][j] = 0.f;
        #pragma unroll
        for (int kt = 0; kt < KT1; kt++) {
            unsigned aH[4], aL[4];
            int ia0 = r0 * (PA1 / 2) + kt * 8 + q;
            int ia1 = (r0 + 8) * (PA1 / 2) + kt * 8 + q;
            aH[0] = zH32[ia0]; aH[1] = zH32[ia1]; aH[2] = zH32[ia0 + 4]; aH[3] = zH32[ia1 + 4];
            aL[0] = zL32[ia0]; aL[1] = zL32[ia1]; aL[2] = zL32[ia0 + 4]; aL[3] = zL32[ia1 + 4];
            #pragma unroll
            for (int nt = 0; nt < NT1; nt++) {
                int n = nh * 64 + nt * 8 + g;
                int ib = n * (PA1 / 2) + kt * 8 + q;
                unsigned bH[2] = {WaH32[ib], WaH32[ib + 4]};
                mma_f16(c1[nt], aH, bH);
                mma_f16(c1[nt], aL, bH);
            }
        }
        // epilogue 1: hidden = relu(c + ba) -> split hi/lo into smem
        #pragma unroll
        for (int nt = 0; nt < NT1; nt++) {
            int col0 = nh * 64 + nt * 8 + 2 * q;
            float b0 = ba_s[col0], b1 = ba_s[col0 + 1];
            float v0 = fmaxf(c1[nt][0] + b0, 0.f);
            float v1 = fmaxf(c1[nt][1] + b1, 0.f);
            float v2 = fmaxf(c1[nt][2] + b0, 0.f);
            float v3 = fmaxf(c1[nt][3] + b1, 0.f);
            unsigned h0, l0, h1, l1;
            split2h(v0, v1, h0, l0);
            split2h(v2, v3, h1, l1);
            int i0 = r0 * (PA2 / 2) + (col0 >> 1);
            int i1 = (r0 + 8) * (PA2 / 2) + (col0 >> 1);
            hH32[i0] = h0; hL32[i0] = l0;
            hH32[i1] = h1; hL32[i1] = l1;
        }
        __syncthreads();

        // ---- stage 2: out = [relu](hidden @ Wb + bb) ----
        float c2[NT2][4];
        #pragma unroll
        for (int nt = 0; nt < NT2; nt++)
            #pragma unroll
            for (int j = 0; j < 4; j++) c2[nt][j] = 0.f;
        #pragma unroll
        for (int kt = 0; kt < KT2; kt++) {
            unsigned aH[4], aL[4];
            int ia0 = r0 * (PA2 / 2) + kt * 8 + q;
            int ia1 = (r0 + 8) * (PA2 / 2) + kt * 8 + q;
            aH[0] = hH32[ia0]; aH[1] = hH32[ia1]; aH[2] = hH32[ia0 + 4]; aH[3] = hH32[ia1 + 4];
            aL[0] = hL32[ia0]; aL[1] = hL32[ia1]; aL[2] = hL32[ia0 + 4]; aL[3] = hL32[ia1 + 4];
            #pragma unroll
            for (int nt = 0; nt < NT2; nt++) {
                int n = nh * (D_OUT / 2) + nt * 8 + g;
                int ib = n * (PA2 / 2) + kt * 8 + q;
                unsigned bH[2] = {WbH32[ib], WbH32[ib + 4]};
                mma_f16(c2[nt], aH, bH);
                mma_f16(c2[nt], aL, bH);
            }
        }
        // epilogue 2
        int node0 = tile0 + r0;
        int node1 = node0 + 8;
        #pragma unroll
        for (int nt = 0; nt < NT2; nt++) {
            int col0 = nh * (D_OUT / 2) + nt * 8 + 2 * q;
            float b0 = bb_s[col0], b1 = bb_s[col0 + 1];
            float x0 = c2[nt][0] + b0, x1 = c2[nt][1] + b1;
            float x2 = c2[nt][2] + b0, x3 = c2[nt][3] + b1;
            if (RELU_OUT) {
                x0 = fmaxf(x0, 0.f); x1 = fmaxf(x1, 0.f);
                x2 = fmaxf(x2, 0.f); x3 = fmaxf(x3, 0.f);
            }
            if constexpr (OUT_HALF) {
                __half* oh = (__half*)out;
                if (node0 < n_nodes)
                    *reinterpret_cast<__half2*>(oh + (size_t)node0 * D_OUT + col0) =
                        __floats2half2_rn(x0, x1);
                if (node1 < n_nodes)
                    *reinterpret_cast<__half2*>(oh + (size_t)node1 * D_OUT + col0) =
                        __floats2half2_rn(x2, x3);
            } else {
                float* of = (float*)out;
                if (node0 < n_nodes)
                    *reinterpret_cast<float2*>(of + (size_t)node0 * D_OUT + col0) =
                        make_float2(x0, x1);
                if (node1 < n_nodes)
                    *reinterpret_cast<float2*>(of + (size_t)node1 * D_OUT + col0) =
                        make_float2(x2, x3);
            }
        }
        __syncthreads();
    }
}

// ---------------------------------- launch -----------------------------------
extern "C" void kernel_launch(void* const* d_in, const int* in_sizes, int n_in,
                              void* d_out, int out_size) {
    const float* x    = (const float*)d_in[0];
    const int*   ei   = (const int*)d_in[1];
    const float* eps1 = (const float*)d_in[2];
    const float* eps2 = (const float*)d_in[3];
    const float* W1a  = (const float*)d_in[4];
    const float* b1a  = (const float*)d_in[5];
    const float* W1b  = (const float*)d_in[6];
    const float* b1b  = (const float*)d_in[7];
    const float* W2a  = (const float*)d_in[8];
    const float* b2a  = (const float*)d_in[9];
    const float* W2b  = (const float*)d_in[10];
    const float* b2b  = (const float*)d_in[11];

    const int n_nodes = in_sizes[0] / 64;
    const int n_edges = in_sizes[1] / 2;
    const int* src = ei;
    const int* dst = ei + n_edges;

    float *z1, *z2;
    __half *xh, *h;
    int *cnt, *off, *cur, *esrc, *bsum;
    cudaGetSymbolAddress((void**)&xh, g_xh);
    cudaGetSymbolAddress((void**)&z1, g_z1);
    cudaGetSymbolAddress((void**)&h,  g_h);
    cudaGetSymbolAddress((void**)&z2, g_z2);
    cudaGetSymbolAddress((void**)&cnt, g_cnt);
    cudaGetSymbolAddress((void**)&off, g_off);
    cudaGetSymbolAddress((void**)&cur, g_cur);
    cudaGetSymbolAddress((void**)&esrc, g_esrc);
    cudaGetSymbolAddress((void**)&bsum, g_bsum);

    const int smem1 = 160768;
    const int smem2 = 192512;
    cudaFuncSetAttribute((const void*)mlp_mma_kernel<64, 128, true, true>,
                         cudaFuncAttributeMaxDynamicSharedMemorySize, smem1);
    cudaFuncSetAttribute((const void*)mlp_mma_kernel<128, 64, false, false>,
                         cudaFuncAttributeMaxDynamicSharedMemorySize, smem2);

    const int nscan = (n_nodes + SCAN_CHUNK - 1) / SCAN_CHUNK;
    const int ntiles = (n_nodes + 127) / 128;
    const int GRID = 148;

    // ---- CSR build + x conversion ----
    hist_kernel<<<(n_edges + 255) / 256, 256>>>(dst, cnt, n_edges);
    scan_part_kernel<<<nscan, 256>>>(cnt, bsum, n_nodes);
    scan_emit_kernel<<<nscan, 256>>>(cnt, bsum, off, cur, n_nodes, n_edges);
    fill_kernel<<<(n_edges + 255) / 256, 256>>>(src, dst, cur, esrc, n_edges);
    {
        int n4 = n_nodes * 64 / 4;
        cvt_half_kernel<<<(n4 + 255) / 256, 256>>>((const float4*)x, (uint2*)xh, n4);
    }

    // ---- layer 1 ----
    {
        int nwarps = (n_nodes + 1) / 2;
        gather64h_kernel<<<(nwarps * 32 + 255) / 256, 256>>>(xh, off, esrc, eps1, z1, n_nodes);
        mlp_mma_kernel<64, 128, true, true><<<GRID, 512, smem1>>>(
            z1, W1a, b1a, W1b, b1b, (void*)h, n_nodes, ntiles);
    }
    // ---- layer 2 ----
    {
        gather128h_kernel<<<(n_nodes * 32 + 255) / 256, 256>>>(h, off, esrc, eps2, z2, n_nodes);
        mlp_mma_kernel<128, 64, false, false><<<GRID, 512, smem2>>>(
            z2, W2a, b2a, W2b, b2b, d_out, n_nodes, ntiles);
    }
}

// round 17
// speedup vs baseline: 1.0462x; 1.0462x over previous
#include <cuda_runtime.h>
#include <cuda_bf16.h>
#include <cuda_fp16.h>
#include <cstdint>

#define N_NODES 100000
#define N_EDGES 800000
#define SCAN_CHUNK 400

// ------------------------- device scratch (no allocs) ------------------------
__device__ __align__(16) float  g_z1[(size_t)N_NODES * 64];
__device__ __align__(16) __half g_h [(size_t)N_NODES * 128];   // layer1 out (fp16)
__device__ __align__(16) float  g_z2[(size_t)N_NODES * 128];
__device__ int g_cnt[N_NODES];          // zero at load; re-zeroed by scan_emit each call
__device__ int g_off[N_NODES + 1];
__device__ int g_rank[N_EDGES];         // per-edge rank within its destination bucket
__device__ int g_esrc[N_EDGES];
__device__ int g_bsum[512];

// ------------------------------ fp16 helpers ---------------------------------
__device__ __forceinline__ unsigned pkh(float x, float y) {
    __half2 h = __floats2half2_rn(x, y);
    return *reinterpret_cast<unsigned*>(&h);
}
__device__ __forceinline__ void split2h(float x, float y, unsigned& hi, unsigned& lo) {
    float xh = __half2float(__float2half_rn(x));
    float yh = __half2float(__float2half_rn(y));
    hi = pkh(x, y);
    lo = pkh(x - xh, y - yh);
}
// m16n8k16 fp16 MMA, fp32 accumulate
__device__ __forceinline__ void mma_f16(float* c, const unsigned* a, const unsigned* b) {
    asm volatile(
        "mma.sync.aligned.m16n8k16.row.col.f32.f16.f16.f32 "
        "{%0,%1,%2,%3}, {%4,%5,%6,%7}, {%8,%9}, {%0,%1,%2,%3};"
        : "+f"(c[0]), "+f"(c[1]), "+f"(c[2]), "+f"(c[3])
        : "r"(a[0]), "r"(a[1]), "r"(a[2]), "r"(a[3]), "r"(b[0]), "r"(b[1]));
}

// ------------------------------ CSR build ------------------------------------
// hist also records each edge's rank within its destination bucket
__global__ void hist_kernel(const int* __restrict__ dst, int* __restrict__ cnt,
                            int* __restrict__ rank, int n_edges) {
    int e = blockIdx.x * blockDim.x + threadIdx.x;
    if (e < n_edges) rank[e] = atomicAdd(&cnt[dst[e]], 1);
}
__global__ void scan_part_kernel(const int* __restrict__ cnt, int* __restrict__ bsum, int n) {
    __shared__ int red[256];
    int b = blockIdx.x, t = threadIdx.x;
    int s = 0;
    for (int i = t; i < SCAN_CHUNK; i += 256) {
        int idx = b * SCAN_CHUNK + i;
        if (idx < n) s += cnt[idx];
    }
    red[t] = s;
    __syncthreads();
    for (int d = 128; d > 0; d >>= 1) {
        if (t < d) red[t] += red[t + d];
        __syncthreads();
    }
    if (t == 0) bsum[b] = red[0];
}
// local scan + inline cross-block base; zeroes cnt after use
__global__ void scan_emit_kernel(int* __restrict__ cnt, const int* __restrict__ bsum,
                                 int* __restrict__ off, int n, int n_edges) {
    __shared__ int s[512];
    __shared__ int red[256];
    int b = blockIdx.x, t = threadIdx.x;
    int acc = 0;
    for (int i = t; i < b; i += 256) acc += bsum[i];
    red[t] = acc;
    __syncthreads();
    for (int d = 128; d > 0; d >>= 1) {
        if (t < d) red[t] += red[t + d];
        __syncthreads();
    }
    int base = red[0];
    #pragma unroll
    for (int h = 0; h < 2; h++) {
        int i = t + h * 256;
        int idx = b * SCAN_CHUNK + i;
        s[i] = (i < SCAN_CHUNK && idx < n) ? cnt[idx] : 0;
    }
    __syncthreads();
    for (int d = 1; d < 512; d <<= 1) {
        int v0 = (t >= d) ? s[t - d] : 0;
        int v1 = s[t + 256 - d];
        __syncthreads();
        s[t] += v0;
        s[t + 256] += v1;
        __syncthreads();
    }
    #pragma unroll
    for (int h = 0; h < 2; h++) {
        int i = t + h * 256;
        int idx = b * SCAN_CHUNK + i;
        if (i < SCAN_CHUNK && idx < n) {
            off[idx] = base + (i ? s[i - 1] : 0);
            cnt[idx] = 0;            // reset for next call
        }
    }
    if (b == 0 && t == 0) off[n] = n_edges;
}
// atomic-free fill: position = off[dst] + rank
__global__ void fill_kernel(const int* __restrict__ src, const int* __restrict__ dst,
                            const int* __restrict__ off, const int* __restrict__ rank,
                            int* __restrict__ esrc, int n_edges) {
    int e = blockIdx.x * blockDim.x + threadIdx.x;
    if (e >= n_edges) return;
    esrc[off[dst[e]] + rank[e]] = src[e];
}

// --------------------- gather aggregation:  z = (1+eps)x + sum ---------------
// layer-1: x fp32, half-warp per node (16 lanes x float4)
__global__ void gather64_kernel(const float* __restrict__ x,
                                const int* __restrict__ off,
                                const int* __restrict__ esrc,
                                const float* __restrict__ eps,
                                float* __restrict__ z, int n_nodes) {
    int gwarp = (blockIdx.x * blockDim.x + threadIdx.x) >> 5;
    int lane = threadIdx.x & 31;
    int node = gwarp * 2 + (lane >> 4);
    int l = lane & 15;
    if (node >= n_nodes) return;
    float4 self = reinterpret_cast<const float4*>(x + (size_t)node * 64)[l];
    float4 acc = make_float4(0.f, 0.f, 0.f, 0.f);
    int e0 = off[node], e1 = off[node + 1];
    for (int e = e0; e < e1; e++) {
        int s = __ldg(&esrc[e]);
        float4 v = reinterpret_cast<const float4*>(x + (size_t)s * 64)[l];
        acc.x += v.x; acc.y += v.y; acc.z += v.z; acc.w += v.w;
    }
    float sc = 1.0f + *eps;
    float4 r = make_float4(fmaf(sc, self.x, acc.x), fmaf(sc, self.y, acc.y),
                           fmaf(sc, self.z, acc.z), fmaf(sc, self.w, acc.w));
    reinterpret_cast<float4*>(z + (size_t)node * 64)[l] = r;
}
// layer-2: h fp16, full warp per node
__global__ void gather128h_kernel(const __half* __restrict__ h,
                                  const int* __restrict__ off,
                                  const int* __restrict__ esrc,
                                  const float* __restrict__ eps,
                                  float* __restrict__ z, int n_nodes) {
    int node = (blockIdx.x * blockDim.x + threadIdx.x) >> 5;
    int l = threadIdx.x & 31;
    if (node >= n_nodes) return;
    const __half2* hrow = reinterpret_cast<const __half2*>(h + (size_t)node * 128) + 2 * l;
    float2 s0 = __half22float2(hrow[0]);
    float2 s1 = __half22float2(hrow[1]);
    float4 acc = make_float4(0.f, 0.f, 0.f, 0.f);
    int e0 = off[node], e1 = off[node + 1];
    for (int e = e0; e < e1; e++) {
        int s = __ldg(&esrc[e]);
        const __half2* vr = reinterpret_cast<const __half2*>(h + (size_t)s * 128) + 2 * l;
        float2 v0 = __half22float2(vr[0]);
        float2 v1 = __half22float2(vr[1]);
        acc.x += v0.x; acc.y += v0.y; acc.z += v1.x; acc.w += v1.y;
    }
    float sc = 1.0f + *eps;
    float4 r = make_float4(fmaf(sc, s0.x, acc.x), fmaf(sc, s0.y, acc.y),
                           fmaf(sc, s1.x, acc.z), fmaf(sc, s1.y, acc.w));
    reinterpret_cast<float4*>(z + (size_t)node * 128)[l] = r;
}

// ----------- MMA MLP: fp16 A-split (exact) x fp16 weights, 2 passes ----------
// Persistent grid, TILE=128 nodes, 512 threads (16 warps). Warp (mt, nh):
// m-tile mt (16 rows), n-half nh. Weights transposed n-major fp16 (single).
// OUT_HALF: write output as __half (layer-1 h buffer), else float.
template <int D_IN, int D_OUT, bool RELU_OUT, bool OUT_HALF>
__global__ void __launch_bounds__(512, 1)
mlp_mma_kernel(const float* __restrict__ z,
               const float* __restrict__ Wa, const float* __restrict__ ba,
               const float* __restrict__ Wb, const float* __restrict__ bb,
               void* __restrict__ out, int n_nodes, int ntiles) {
    constexpr int DH = 128, TILE = 128, THREADS = 512;
    constexpr int PA1 = D_IN + 8;
    constexpr int PA2 = DH + 8;
    constexpr int KT1 = D_IN / 16, KT2 = DH / 16;
    constexpr int NT1 = 8;            // stage1: 64 cols per n-half / 8
    constexpr int NT2 = D_OUT / 16;   // stage2 n-tiles per half
    constexpr int SZ_WaT = DH * PA1 * 2;
    constexpr int SZ_WbT = D_OUT * PA2 * 2;
    constexpr int SZ_Z = TILE * PA1 * 2;
    constexpr int SZ_H = TILE * PA2 * 2;
    constexpr int O_WaH = 0;
    constexpr int O_WbH = SZ_WaT;
    constexpr int O_ZH = O_WbH + SZ_WbT, O_ZL = O_ZH + SZ_Z;
    constexpr int O_HH = O_ZL + SZ_Z, O_HL = O_HH + SZ_H;
    constexpr int O_BA = O_HL + SZ_H, O_BB = O_BA + DH * 4;

    extern __shared__ char sm[];
    unsigned short* WaH = (unsigned short*)(sm + O_WaH);
    unsigned short* WbH = (unsigned short*)(sm + O_WbH);
    const unsigned* WaH32 = (const unsigned*)WaH;
    const unsigned* WbH32 = (const unsigned*)WbH;
    unsigned* zH32 = (unsigned*)(sm + O_ZH);
    unsigned* zL32 = (unsigned*)(sm + O_ZL);
    unsigned* hH32 = (unsigned*)(sm + O_HH);
    unsigned* hL32 = (unsigned*)(sm + O_HL);
    float* ba_s = (float*)(sm + O_BA);
    float* bb_s = (float*)(sm + O_BB);

    const int tid = threadIdx.x;
    const int wid = tid >> 5, lane = tid & 31;
    const int g = lane >> 2, q = lane & 3;
    const int mt = wid >> 1, nh = wid & 1;
    const int r0 = mt * 16 + g;

    // ---- stage weights once per CTA (fp16, n-major) ----
    for (int i = tid; i < D_IN * DH; i += THREADS) {
        int k = i / DH, n = i % DH;
        WaH[n * PA1 + k] = __half_as_ushort(__float2half_rn(Wa[i]));
    }
    for (int i = tid; i < DH * D_OUT; i += THREADS) {
        int k = i / D_OUT, n = i % D_OUT;
        WbH[n * PA2 + k] = __half_as_ushort(__float2half_rn(Wb[i]));
    }
    if (tid < DH) ba_s[tid] = ba[tid];
    if (tid < D_OUT) bb_s[tid] = bb[tid];
    __syncthreads();

    for (int t = blockIdx.x; t < ntiles; t += gridDim.x) {
        const int tile0 = t * TILE;

        // ---- stage z tile: split into hi/lo fp16 [row][k] ----
        for (int i = tid; i < TILE * (D_IN / 4); i += THREADS) {
            int r = i / (D_IN / 4);
            int kc = i % (D_IN / 4);
            int node = tile0 + r;
            float4 v = (node < n_nodes)
                     ? reinterpret_cast<const float4*>(z + (size_t)node * D_IN)[kc]
                     : make_float4(0.f, 0.f, 0.f, 0.f);
            unsigned h0, l0, h1, l1;
            split2h(v.x, v.y, h0, l0);
            split2h(v.z, v.w, h1, l1);
            int idx = r * (PA1 / 2) + kc * 2;
            *reinterpret_cast<uint2*>(zH32 + idx) = make_uint2(h0, h1);
            *reinterpret_cast<uint2*>(zL32 + idx) = make_uint2(l0, l1);
        }
        __syncthreads();

        // ---- stage 1: hidden = relu(z @ Wa + ba) ----
        float c1[NT1][4];
        #pragma unroll
        for (int nt = 0; nt < NT1; nt++)
            #pragma unroll
            for (int j = 0; j < 4; j++) c1[nt][j] = 0.f;
        #pragma unroll
        for (int kt = 0; kt < KT1; kt++) {
            unsigned aH[4], aL[4];
            int ia0 = r0 * (PA1 / 2) + kt * 8 + q;
            int ia1 = (r0 + 8) * (PA1 / 2) + kt * 8 + q;
            aH[0] = zH32[ia0]; aH[1] = zH32[ia1]; aH[2] = zH32[ia0 + 4]; aH[3] = zH32[ia1 + 4];
            aL[0] = zL32[ia0]; aL[1] = zL32[ia1]; aL[2] = zL32[ia0 + 4]; aL[3] = zL32[ia1 + 4];
            #pragma unroll
            for (int nt = 0; nt < NT1; nt++) {
                int n = nh * 64 + nt * 8 + g;
                int ib = n * (PA1 / 2) + kt * 8 + q;
                unsigned bH[2] = {WaH32[ib], WaH32[ib + 4]};
                mma_f16(c1[nt], aH, bH);
                mma_f16(c1[nt], aL, bH);
            }
        }
        // epilogue 1: hidden = relu(c + ba) -> split hi/lo into smem
        #pragma unroll
        for (int nt = 0; nt < NT1; nt++) {
            int col0 = nh * 64 + nt * 8 + 2 * q;
            float b0 = ba_s[col0], b1 = ba_s[col0 + 1];
            float v0 = fmaxf(c1[nt][0] + b0, 0.f);
            float v1 = fmaxf(c1[nt][1] + b1, 0.f);
            float v2 = fmaxf(c1[nt][2] + b0, 0.f);
            float v3 = fmaxf(c1[nt][3] + b1, 0.f);
            unsigned h0, l0, h1, l1;
            split2h(v0, v1, h0, l0);
            split2h(v2, v3, h1, l1);
            int i0 = r0 * (PA2 / 2) + (col0 >> 1);
            int i1 = (r0 + 8) * (PA2 / 2) + (col0 >> 1);
            hH32[i0] = h0; hL32[i0] = l0;
            hH32[i1] = h1; hL32[i1] = l1;
        }
        __syncthreads();

        // ---- stage 2: out = [relu](hidden @ Wb + bb) ----
        float c2[NT2][4];
        #pragma unroll
        for (int nt = 0; nt < NT2; nt++)
            #pragma unroll
            for (int j = 0; j < 4; j++) c2[nt][j] = 0.f;
        #pragma unroll
        for (int kt = 0; kt < KT2; kt++) {
            unsigned aH[4], aL[4];
            int ia0 = r0 * (PA2 / 2) + kt * 8 + q;
            int ia1 = (r0 + 8) * (PA2 / 2) + kt * 8 + q;
            aH[0] = hH32[ia0]; aH[1] = hH32[ia1]; aH[2] = hH32[ia0 + 4]; aH[3] = hH32[ia1 + 4];
            aL[0] = hL32[ia0]; aL[1] = hL32[ia1]; aL[2] = hL32[ia0 + 4]; aL[3] = hL32[ia1 + 4];
            #pragma unroll
            for (int nt = 0; nt < NT2; nt++) {
                int n = nh * (D_OUT / 2) + nt * 8 + g;
                int ib = n * (PA2 / 2) + kt * 8 + q;
                unsigned bH[2] = {WbH32[ib], WbH32[ib + 4]};
                mma_f16(c2[nt], aH, bH);
                mma_f16(c2[nt], aL, bH);
            }
        }
        // epilogue 2
        int node0 = tile0 + r0;
        int node1 = node0 + 8;
        #pragma unroll
        for (int nt = 0; nt < NT2; nt++) {
            int col0 = nh * (D_OUT / 2) + nt * 8 + 2 * q;
            float b0 = bb_s[col0], b1 = bb_s[col0 + 1];
            float x0 = c2[nt][0] + b0, x1 = c2[nt][1] + b1;
            float x2 = c2[nt][2] + b0, x3 = c2[nt][3] + b1;
            if (RELU_OUT) {
                x0 = fmaxf(x0, 0.f); x1 = fmaxf(x1, 0.f);
                x2 = fmaxf(x2, 0.f); x3 = fmaxf(x3, 0.f);
            }
            if constexpr (OUT_HALF) {
                __half* oh = (__half*)out;
                if (node0 < n_nodes)
                    *reinterpret_cast<__half2*>(oh + (size_t)node0 * D_OUT + col0) =
                        __floats2half2_rn(x0, x1);
                if (node1 < n_nodes)
                    *reinterpret_cast<__half2*>(oh + (size_t)node1 * D_OUT + col0) =
                        __floats2half2_rn(x2, x3);
            } else {
                float* of = (float*)out;
                if (node0 < n_nodes)
                    *reinterpret_cast<float2*>(of + (size_t)node0 * D_OUT + col0) =
                        make_float2(x0, x1);
                if (node1 < n_nodes)
                    *reinterpret_cast<float2*>(of + (size_t)node1 * D_OUT + col0) =
                        make_float2(x2, x3);
            }
        }
        __syncthreads();
    }
}

// ---------------------------------- launch -----------------------------------
extern "C" void kernel_launch(void* const* d_in, const int* in_sizes, int n_in,
                              void* d_out, int out_size) {
    const float* x    = (const float*)d_in[0];
    const int*   ei   = (const int*)d_in[1];
    const float* eps1 = (const float*)d_in[2];
    const float* eps2 = (const float*)d_in[3];
    const float* W1a  = (const float*)d_in[4];
    const float* b1a  = (const float*)d_in[5];
    const float* W1b  = (const float*)d_in[6];
    const float* b1b  = (const float*)d_in[7];
    const float* W2a  = (const float*)d_in[8];
    const float* b2a  = (const float*)d_in[9];
    const float* W2b  = (const float*)d_in[10];
    const float* b2b  = (const float*)d_in[11];

    const int n_nodes = in_sizes[0] / 64;
    const int n_edges = in_sizes[1] / 2;
    const int* src = ei;
    const int* dst = ei + n_edges;

    float *z1, *z2;
    __half* h;
    int *cnt, *off, *rank, *esrc, *bsum;
    cudaGetSymbolAddress((void**)&z1, g_z1);
    cudaGetSymbolAddress((void**)&h,  g_h);
    cudaGetSymbolAddress((void**)&z2, g_z2);
    cudaGetSymbolAddress((void**)&cnt, g_cnt);
    cudaGetSymbolAddress((void**)&off, g_off);
    cudaGetSymbolAddress((void**)&rank, g_rank);
    cudaGetSymbolAddress((void**)&esrc, g_esrc);
    cudaGetSymbolAddress((void**)&bsum, g_bsum);

    const int smem1 = 160768;
    const int smem2 = 192512;
    cudaFuncSetAttribute((const void*)mlp_mma_kernel<64, 128, true, true>,
                         cudaFuncAttributeMaxDynamicSharedMemorySize, smem1);
    cudaFuncSetAttribute((const void*)mlp_mma_kernel<128, 64, false, false>,
                         cudaFuncAttributeMaxDynamicSharedMemorySize, smem2);

    const int nscan = (n_nodes + SCAN_CHUNK - 1) / SCAN_CHUNK;
    const int ntiles = (n_nodes + 127) / 128;
    const int GRID = 148;

    // ---- CSR build (cnt zero on entry; scan_emit re-zeroes it) ----
    hist_kernel<<<(n_edges + 255) / 256, 256>>>(dst, cnt, rank, n_edges);
    scan_part_kernel<<<nscan, 256>>>(cnt, bsum, n_nodes);
    scan_emit_kernel<<<nscan, 256>>>(cnt, bsum, off, n_nodes, n_edges);
    fill_kernel<<<(n_edges + 255) / 256, 256>>>(src, dst, off, rank, esrc, n_edges);

    // ---- layer 1 ----
    {
        int nwarps = (n_nodes + 1) / 2;
        gather64_kernel<<<(nwarps * 32 + 255) / 256, 256>>>(x, off, esrc, eps1, z1, n_nodes);
        mlp_mma_kernel<64, 128, true, true><<<GRID, 512, smem1>>>(
            z1, W1a, b1a, W1b, b1b, (void*)h, n_nodes, ntiles);
    }
    // ---- layer 2 ----
    {
        gather128h_kernel<<<(n_nodes * 32 + 255) / 256, 256>>>(h, off, esrc, eps2, z2, n_nodes);
        mlp_mma_kernel<128, 64, false, false><<<GRID, 512, smem2>>>(
            z2, W2a, b2a, W2b, b2b, d_out, n_nodes, ntiles);
    }
}